// round 1
// baseline (speedup 1.0000x reference)
#include <cuda_runtime.h>
#include <math.h>

// Shapes
#define V_SZ 50257
#define E_SZ 512
#define H_SZ 1024
#define C_SZ 1024
#define S_SZ 2048
#define G_SZ 4096           // 4*H
#define NCH 32              // chunks for two-stage reductions

// ---------------- scratch (device globals; no allocation allowed) -------------
__device__ __align__(16) float g_gates[G_SZ];
__device__ __align__(16) float g_upart[3][NCH][C_SZ];
__device__ __align__(16) float g_u[3][C_SZ];
__device__            float g_bq[3];
__device__ __align__(16) float g_e[3][S_SZ];
__device__ __align__(16) float g_a[3][S_SZ];
__device__ __align__(16) float g_wpart[3][NCH][C_SZ];
__device__ __align__(16) float g_concat_in[4 * H_SZ];   // [q | lctx | rctx | lemma]
__device__ __align__(16) float g_concat_out[H_SZ];

// ---------------- helpers ------------------------------------------------------
__device__ __forceinline__ float warp_sum(float v) {
#pragma unroll
    for (int o = 16; o; o >>= 1) v += __shfl_xor_sync(0xffffffffu, v, o);
    return v;
}
__device__ __forceinline__ float warp_max(float v) {
#pragma unroll
    for (int o = 16; o; o >>= 1) v = fmaxf(v, __shfl_xor_sync(0xffffffffu, v, o));
    return v;
}
__device__ __forceinline__ float sigf(float x) { return 1.0f / (1.0f + expf(-x)); }

// ---------------- K1/K3: LSTM gate GEMV -------------------------------------
// g[r] = Wih[r,:lenA]·x + Whh[r,:H]·h + bih[r] + bhh[r],  r in [0,4096)
// warp-per-row, 8 warps/block, grid = 512
__global__ void k_gates(const float* __restrict__ Wih, int lenA,
                        const float* __restrict__ Whh,
                        const float* __restrict__ bih, const float* __restrict__ bhh,
                        const float* __restrict__ xbase, const int* __restrict__ idx,
                        const float* __restrict__ hprev) {
    extern __shared__ float sh[];  // lenA + H floats
    const float* x = idx ? (xbase + (size_t)idx[0] * lenA) : xbase;
    const int tid = threadIdx.x;
    for (int i = tid; i < lenA; i += blockDim.x) sh[i] = x[i];
    for (int i = tid; i < H_SZ; i += blockDim.x) sh[lenA + i] = hprev[i];
    __syncthreads();

    const int row  = blockIdx.x * 8 + (tid >> 5);
    const int lane = tid & 31;
    const float4* a  = (const float4*)(Wih + (size_t)row * lenA);
    const float4* b  = (const float4*)(Whh + (size_t)row * H_SZ);
    const float4* x4 = (const float4*)sh;
    const float4* h4 = (const float4*)(sh + lenA);
    const int nA = lenA >> 2;

    float s = 0.f;
    for (int i = lane; i < nA; i += 32) {
        float4 w = a[i], v = x4[i];
        s += w.x * v.x + w.y * v.y + w.z * v.z + w.w * v.w;
    }
#pragma unroll 4
    for (int i = lane; i < (H_SZ >> 2); i += 32) {
        float4 w = b[i], v = h4[i];
        s += w.x * v.x + w.y * v.y + w.z * v.z + w.w * v.w;
    }
    s = warp_sum(s);
    if (lane == 0) g_gates[row] = s + bih[row] + bhh[row];
}

// ---------------- K2/K4: LSTM activation --------------------------------------
// block = 1024 threads; writes h,c directly into d_out; optionally copies q
__global__ void k_lstm_act(const float* __restrict__ cprev,
                           float* __restrict__ hout, float* __restrict__ cout,
                           int copy_q) {
    const int j = threadIdx.x;
    const float ig = sigf(g_gates[j]);
    const float fg = sigf(g_gates[H_SZ + j]);
    const float gg = tanhf(g_gates[2 * H_SZ + j]);
    const float og = sigf(g_gates[3 * H_SZ + j]);
    const float c = fg * cprev[j] + ig * gg;
    const float h = og * tanhf(c);
    cout[j] = c;
    hout[j] = h;
    if (copy_q) g_concat_in[j] = h;   // q = rnn_output, first concat segment
}

// ---------------- K5: u = W^T q  (partials) ------------------------------------
// grid (NCH, 3), block 256; thread owns 4 columns (float4); 32 h-rows per chunk
__global__ void k_u_partial(const float* __restrict__ WL,
                            const float* __restrict__ WR,
                            const float* __restrict__ WM) {
    __shared__ float shq[32];
    const int hd = blockIdx.y;
    const float* W = (hd == 0) ? WL : (hd == 1) ? WR : WM;
    const int h0 = blockIdx.x * 32;
    const int tid = threadIdx.x;
    if (tid < 32) shq[tid] = g_concat_in[h0 + tid];
    __syncthreads();

    const float4* W4 = (const float4*)W;
    float4 acc = make_float4(0.f, 0.f, 0.f, 0.f);
#pragma unroll 8
    for (int k = 0; k < 32; k++) {
        float4 w = W4[(size_t)(h0 + k) * (C_SZ >> 2) + tid];
        float qv = shq[k];
        acc.x += w.x * qv; acc.y += w.y * qv; acc.z += w.z * qv; acc.w += w.w * qv;
    }
    ((float4*)g_upart[hd][blockIdx.x])[tid] = acc;
}

// ---------------- K5b: reduce u + compute bq = b·q ------------------------------
// grid 3, block 1024
__global__ void k_u_reduce(const float* __restrict__ bL,
                           const float* __restrict__ bR,
                           const float* __restrict__ bM) {
    __shared__ float sh[32];
    const int hd = blockIdx.x;
    const int c = threadIdx.x;
    float s = 0.f;
#pragma unroll
    for (int k = 0; k < NCH; k++) s += g_upart[hd][k][c];
    g_u[hd][c] = s;

    const float* bias = (hd == 0) ? bL : (hd == 1) ? bR : bM;
    float v = bias[c] * g_concat_in[c];
    v = warp_sum(v);
    if ((c & 31) == 0) sh[c >> 5] = v;
    __syncthreads();
    if (c < 32) {
        float t = sh[c];
        t = warp_sum(t);
        if (c == 0) g_bq[hd] = t;
    }
}

// ---------------- K6: e[hd][s] = ctx[s,:]·u[hd] + bq[hd] ------------------------
// warp-per-row, 8 warps/block, grid = 3*2048/8 = 768
__global__ void k_e(const float* __restrict__ ctxL,
                    const float* __restrict__ ctxR,
                    const float* __restrict__ ctxM) {
    __shared__ float su[C_SZ];
    const int tid  = threadIdx.x;
    const int row  = blockIdx.x * 8 + (tid >> 5);
    const int hd   = row >> 11;           // 2048 rows per head, no block straddling
    const int srow = row & (S_SZ - 1);
    for (int i = tid; i < C_SZ; i += blockDim.x) su[i] = g_u[hd][i];
    __syncthreads();

    const float* ctx = (hd == 0) ? ctxL : (hd == 1) ? ctxR : ctxM;
    const float4* c4 = (const float4*)(ctx + (size_t)srow * C_SZ);
    const float4* u4 = (const float4*)su;
    const int lane = tid & 31;
    float s = 0.f;
#pragma unroll 4
    for (int i = lane; i < (C_SZ >> 2); i += 32) {
        float4 w = c4[i], v = u4[i];
        s += w.x * v.x + w.y * v.y + w.z * v.z + w.w * v.w;
    }
    s = warp_sum(s);
    if (lane == 0) g_e[hd][srow] = s + g_bq[hd];
}

// ---------------- K7: softmax per head ------------------------------------------
// grid 3, block 1024 (2 elems/thread)
__global__ void k_softmax() {
    __shared__ float shm[32];
    __shared__ float shs[32];
    __shared__ float redM, redZ;
    const int hd = blockIdx.x, t = threadIdx.x;
    const float e0 = g_e[hd][t], e1 = g_e[hd][t + 1024];

    float m = fmaxf(e0, e1);
    m = warp_max(m);
    if ((t & 31) == 0) shm[t >> 5] = m;
    __syncthreads();
    if (t < 32) {
        float v = shm[t];
        v = warp_max(v);
        if (t == 0) redM = v;
    }
    __syncthreads();
    const float M = redM;

    const float x0 = expf(e0 - M), x1 = expf(e1 - M);
    float s = x0 + x1;
    s = warp_sum(s);
    if ((t & 31) == 0) shs[t >> 5] = s;
    __syncthreads();
    if (t < 32) {
        float v = shs[t];
        v = warp_sum(v);
        if (t == 0) redZ = v;
    }
    __syncthreads();
    const float inv = 1.0f / redZ;
    g_a[hd][t] = x0 * inv;
    g_a[hd][t + 1024] = x1 * inv;
}

// ---------------- K8: weighted column sum partials ------------------------------
// grid (NCH, 3), block 256, thread owns 4 columns; 64 s-rows per chunk
__global__ void k_wsum_part(const float* __restrict__ ctxL,
                            const float* __restrict__ ctxR,
                            const float* __restrict__ ctxM) {
    __shared__ float sha[64];
    const int hd = blockIdx.y;
    const int s0 = blockIdx.x * 64;
    const int tid = threadIdx.x;
    if (tid < 64) sha[tid] = g_a[hd][s0 + tid];
    __syncthreads();

    const float* ctx = (hd == 0) ? ctxL : (hd == 1) ? ctxR : ctxM;
    const float4* c4 = (const float4*)ctx;
    float4 acc = make_float4(0.f, 0.f, 0.f, 0.f);
#pragma unroll 8
    for (int k = 0; k < 64; k++) {
        float4 v = c4[(size_t)(s0 + k) * (C_SZ >> 2) + tid];
        float av = sha[k];
        acc.x += v.x * av; acc.y += v.y * av; acc.z += v.z * av; acc.w += v.w * av;
    }
    ((float4*)g_wpart[hd][blockIdx.x])[tid] = acc;
}

// ---------------- K9: reduce partials -> concat segments ------------------------
// grid 3, block 1024
__global__ void k_wsum_reduce() {
    const int hd = blockIdx.x, c = threadIdx.x;
    float s = 0.f;
#pragma unroll
    for (int k = 0; k < NCH; k++) s += g_wpart[hd][k][c];
    g_concat_in[H_SZ * (1 + hd) + c] = s;
}

// ---------------- K10: concat_out = tanh(W_concat @ concat_in + b) --------------
// warp-per-row, rows=1024, dot=4096; grid 128, block 256
__global__ void k_concat_gemv(const float* __restrict__ Wc,
                              const float* __restrict__ bc) {
    __shared__ float shx[4 * H_SZ];
    const int tid = threadIdx.x;
    for (int i = tid; i < 4 * H_SZ; i += blockDim.x) shx[i] = g_concat_in[i];
    __syncthreads();

    const int row  = blockIdx.x * 8 + (tid >> 5);
    const int lane = tid & 31;
    const float4* a  = (const float4*)(Wc + (size_t)row * 4 * H_SZ);
    const float4* x4 = (const float4*)shx;
    float s = 0.f;
#pragma unroll 4
    for (int i = lane; i < H_SZ; i += 32) {   // 4096/4 = 1024 float4
        float4 w = a[i], v = x4[i];
        s += w.x * v.x + w.y * v.y + w.z * v.z + w.w * v.w;
    }
    s = warp_sum(s);
    if (lane == 0) g_concat_out[row] = tanhf(s + bc[row]);
}

// ---------------- K11: output = W_out @ concat_out + b_out ----------------------
// warp-per-row, rows=50257; grid 6283, block 256
__global__ void k_out_gemv(const float* __restrict__ Wo,
                           const float* __restrict__ bo,
                           float* __restrict__ out) {
    __shared__ float shx[H_SZ];
    const int tid = threadIdx.x;
    for (int i = tid; i < H_SZ; i += blockDim.x) shx[i] = g_concat_out[i];
    __syncthreads();

    const int row = blockIdx.x * 8 + (tid >> 5);
    if (row >= V_SZ) return;
    const int lane = tid & 31;
    const float4* a  = (const float4*)(Wo + (size_t)row * H_SZ);
    const float4* x4 = (const float4*)shx;
    float s = 0.f;
#pragma unroll
    for (int i = lane; i < (H_SZ >> 2); i += 32) {
        float4 w = a[i], v = x4[i];
        s += w.x * v.x + w.y * v.y + w.z * v.z + w.w * v.w;
    }
    s = warp_sum(s);
    if (lane == 0) out[row] = s + bo[row];
}

// ================================================================================
extern "C" void kernel_launch(void* const* d_in, const int* in_sizes, int n_in,
                              void* d_out, int out_size) {
    const int*   input_ids = (const int*)  d_in[0];
    const float* h0        = (const float*)d_in[1];   // [2,1,H]
    const float* c0        = (const float*)d_in[2];   // [2,1,H]
    const float* ctxL      = (const float*)d_in[3];   // [S,C]
    const float* ctxR      = (const float*)d_in[4];
    const float* ctxM      = (const float*)d_in[5];   // lemma_outputs [S,L]
    const float* emb       = (const float*)d_in[6];   // [V,E]
    const float* Wih0      = (const float*)d_in[7];
    const float* Whh0      = (const float*)d_in[8];
    const float* bih0      = (const float*)d_in[9];
    const float* bhh0      = (const float*)d_in[10];
    const float* Wih1      = (const float*)d_in[11];
    const float* Whh1      = (const float*)d_in[12];
    const float* bih1      = (const float*)d_in[13];
    const float* bhh1      = (const float*)d_in[14];
    const float* WL        = (const float*)d_in[15];
    const float* bL        = (const float*)d_in[16];
    const float* WR        = (const float*)d_in[17];
    const float* bR        = (const float*)d_in[18];
    const float* WM        = (const float*)d_in[19];
    const float* bM        = (const float*)d_in[20];
    const float* Wc        = (const float*)d_in[21];
    const float* bc        = (const float*)d_in[22];
    const float* Wo        = (const float*)d_in[23];
    const float* bo        = (const float*)d_in[24];

    float* out   = (float*)d_out;            // [V]
    float* h_new = out + V_SZ;               // [2*H]
    float* c_new = out + V_SZ + 2 * H_SZ;    // [2*H]

    // ---- LSTM layer 0: x = embedding[input_ids]
    k_gates<<<512, 256, (E_SZ + H_SZ) * sizeof(float)>>>(
        Wih0, E_SZ, Whh0, bih0, bhh0, emb, input_ids, h0);
    k_lstm_act<<<1, 1024>>>(c0, h_new, c_new, 0);

    // ---- LSTM layer 1: x = h_0 (already in d_out)
    k_gates<<<512, 256, (H_SZ + H_SZ) * sizeof(float)>>>(
        Wih1, H_SZ, Whh1, bih1, bhh1, h_new, nullptr, h0 + H_SZ);
    k_lstm_act<<<1, 1024>>>(c0 + H_SZ, h_new + H_SZ, c_new + H_SZ, 1);

    // ---- attention: u = W^T q, bq = b·q
    k_u_partial<<<dim3(NCH, 3), 256>>>(WL, WR, WM);
    k_u_reduce<<<3, 1024>>>(bL, bR, bM);

    // ---- e = ctx·u + bq ; softmax ; weighted column sums
    k_e<<<768, 256>>>(ctxL, ctxR, ctxM);
    k_softmax<<<3, 1024>>>();
    k_wsum_part<<<dim3(NCH, 3), 256>>>(ctxL, ctxR, ctxM);
    k_wsum_reduce<<<3, 1024>>>();

    // ---- concat GEMV + tanh, then vocab GEMV
    k_concat_gemv<<<128, 256>>>(Wc, bc);
    k_out_gemv<<<(V_SZ + 7) / 8, 256>>>(Wo, bo, out);
}